// round 14
// baseline (speedup 1.0000x reference)
#include <cuda_runtime.h>

#define FULL 0xffffffffu
#define NQ 8

// ---------------------------------------------------------------------------
// Packed gate constants (written by precompute kernel).
// g_pk[br][54] float2:
//   [0..11]  U3(1) lane gate: [hi*6 + e*3 + v], e=0 diag, e=1 offdiag,
//            v: 0=(E.x,E.x) 1=(-E.y,-E.y) 2=(E.y,E.y)
//   [12..17] U3(5) horizontal: P0x,P0yn,P0yp,Q0x,Q0yn,Q0yp
//   [18..41] A gate (q3, lane-sel): [hi*12 + e*3 + v], e=E00,E01,E10,E11
//   [42..53] B gate (q7, per-half MB0/MB1 packed)
// g_obsp[br][w][6]: dup(a), dup(-a), dup(2b.x), dup(-2b.y), dup(2b.y), 0
// ---------------------------------------------------------------------------
__device__ float2 g_pk[3][54];
__device__ float2 g_obsp[3][2][6];
__device__ float2 g_cr[3][10];     // (cos(t/2), sin(t/2)) per branch
__device__ float  g_hz[8];         // RZ half-angles 0..7 (used 0..6)

// ---------------------------------------------------------------------------
// packed f32x2 helpers
// ---------------------------------------------------------------------------
static __device__ __forceinline__ float2 f2mul(float2 a, float2 b) {
    float2 d;
    asm("{.reg .b64 A,B,D;\n\t"
        "mov.b64 A,{%2,%3};\n\t"
        "mov.b64 B,{%4,%5};\n\t"
        "mul.rn.f32x2 D,A,B;\n\t"
        "mov.b64 {%0,%1},D;}"
        : "=f"(d.x), "=f"(d.y)
        : "f"(a.x), "f"(a.y), "f"(b.x), "f"(b.y));
    return d;
}
static __device__ __forceinline__ float2 f2fma(float2 a, float2 b, float2 c) {
    float2 d;
    asm("{.reg .b64 A,B,C,D;\n\t"
        "mov.b64 A,{%2,%3};\n\t"
        "mov.b64 B,{%4,%5};\n\t"
        "mov.b64 C,{%6,%7};\n\t"
        "fma.rn.f32x2 D,A,B,C;\n\t"
        "mov.b64 {%0,%1},D;}"
        : "=f"(d.x), "=f"(d.y)
        : "f"(a.x), "f"(a.y), "f"(b.x), "f"(b.y), "f"(c.x), "f"(c.y));
    return d;
}
static __device__ __forceinline__ float2 swp(float2 v) { return make_float2(v.y, v.x); }
static __device__ __forceinline__ float2 dup(float x)  { return make_float2(x, x); }

static __device__ __forceinline__ float2 cmul(float2 a, float2 b) {
    return make_float2(fmaf(a.x, b.x, -a.y * b.y), fmaf(a.x, b.y, a.y * b.x));
}
static __device__ __forceinline__ float2 cjmul(float2 u, float2 v) {   // conj(u)*v
    return make_float2(fmaf(u.x, v.x,  u.y * v.y), fmaf(u.x, v.y, -u.y * v.x));
}

static __device__ __forceinline__ float2 shfl2(float2 v, int lm) {
    return make_float2(__shfl_xor_sync(FULL, v.x, lm),
                       __shfl_xor_sync(FULL, v.y, lm));
}

// ---------------------------------------------------------------------------
// Precompute kernel
// ---------------------------------------------------------------------------
__global__ void qcnn_precompute(const float* __restrict__ crx, const float* __restrict__ u3x,
                                const float* __restrict__ cry, const float* __restrict__ u3y,
                                const float* __restrict__ crz, const float* __restrict__ u3z) {
    __shared__ float2 su3[3][6][4];
    __shared__ float2 scr[3][10];
    int t = threadIdx.x;
    if (t < 30) {
        int br = t / 10, k = t % 10;
        const float* p = (br == 0) ? crx : (br == 1) ? cry : crz;
        float s, c; sincosf(0.5f * p[k], &s, &c);
        scr[br][k] = make_float2(c, s);
        g_cr[br][k] = make_float2(c, s);
        if (br == 2 && k < 8) g_hz[k] = 0.5f * crz[k];
    }
    if (t >= 32 && t < 50) {
        int i = t - 32, br = i / 6, k = i % 6;
        const float* u3p = (br == 0) ? u3x : (br == 1) ? u3y : u3z;
        float th = u3p[k*3+0], ph = u3p[k*3+1], lm = u3p[k*3+2];
        float st, ct, sp, cp, sl, cl, spl, cpl;
        sincosf(0.5f * th, &st, &ct);
        sincosf(ph, &sp, &cp);
        sincosf(lm, &sl, &cl);
        sincosf(ph + lm, &spl, &cpl);
        su3[br][k][0] = make_float2(ct, 0.f);
        su3[br][k][1] = make_float2(-cl * st, -sl * st);
        su3[br][k][2] = make_float2(cp * st, sp * st);
        su3[br][k][3] = make_float2(cpl * ct, spl * ct);
    }
    __syncthreads();
    if (t < 3) {
        int br = t;
        const float2* U1  = su3[br][0];   // wire 1
        const float2* U3w = su3[br][1];   // wire 3
        const float2* U5  = su3[br][2];   // wire 5
        const float2* U7  = su3[br][3];   // wire 7

        // fused MA1 = R(1,3)*U3(3), MB1 = R(5,7)*U3(7)
        float2 MA1[4], MB1[4];
        for (int which = 0; which < 2; which++) {
            float2 cs = scr[br][7 + which];
            float2 R[4];
            if (br == 0) {        // RX
                R[0] = make_float2(cs.x, 0.f);  R[1] = make_float2(0.f, -cs.y);
                R[2] = make_float2(0.f, -cs.y); R[3] = make_float2(cs.x, 0.f);
            } else if (br == 1) { // RY
                R[0] = make_float2(cs.x, 0.f);  R[1] = make_float2(-cs.y, 0.f);
                R[2] = make_float2(cs.y, 0.f);  R[3] = make_float2(cs.x, 0.f);
            } else {              // RZ
                R[0] = make_float2(cs.x, -cs.y); R[1] = make_float2(0.f, 0.f);
                R[2] = make_float2(0.f, 0.f);    R[3] = make_float2(cs.x, cs.y);
            }
            const float2* U = (which == 0) ? U3w : U7;
            float2* D = (which == 0) ? MA1 : MB1;
            float2 d0a = cmul(R[0], U[0]), d0b = cmul(R[1], U[2]);
            float2 d1a = cmul(R[0], U[1]), d1b = cmul(R[1], U[3]);
            float2 d2a = cmul(R[2], U[0]), d2b = cmul(R[3], U[2]);
            float2 d3a = cmul(R[2], U[1]), d3b = cmul(R[3], U[3]);
            D[0] = make_float2(d0a.x + d0b.x, d0a.y + d0b.y);
            D[1] = make_float2(d1a.x + d1b.x, d1a.y + d1b.y);
            D[2] = make_float2(d2a.x + d2b.x, d2a.y + d2b.y);
            D[3] = make_float2(d3a.x + d3b.x, d3a.y + d3b.y);
        }

        float2* P = g_pk[br];
        // U3(1) lane gate
        {
            float2 es[4] = {U1[0], U1[1], U1[3], U1[2]};
            for (int i = 0; i < 4; i++) {
                P[i*3 + 0] = make_float2(es[i].x, es[i].x);
                P[i*3 + 1] = make_float2(-es[i].y, -es[i].y);
                P[i*3 + 2] = make_float2(es[i].y, es[i].y);
            }
        }
        // U3(5) horizontal
        P[12] = make_float2(U5[0].x, U5[3].x);
        P[13] = make_float2(-U5[0].y, -U5[3].y);
        P[14] = make_float2(U5[0].y, U5[3].y);
        P[15] = make_float2(U5[1].x, U5[2].x);
        P[16] = make_float2(-U5[1].y, -U5[2].y);
        P[17] = make_float2(U5[1].y, U5[2].y);
        // A gate: hi=0 -> U3(3), hi=1 -> MA1
        for (int e = 0; e < 4; e++) {
            float2 E = U3w[e];
            P[18 + e*3 + 0] = make_float2(E.x, E.x);
            P[18 + e*3 + 1] = make_float2(-E.y, -E.y);
            P[18 + e*3 + 2] = make_float2(E.y, E.y);
            E = MA1[e];
            P[30 + e*3 + 0] = make_float2(E.x, E.x);
            P[30 + e*3 + 1] = make_float2(-E.y, -E.y);
            P[30 + e*3 + 2] = make_float2(E.y, E.y);
        }
        // B gate: per-half packed (MB0=U7 lo, MB1 hi)
        for (int e = 0; e < 4; e++) {
            float2 lo = U7[e], hi = MB1[e];
            P[42 + e*3 + 0] = make_float2(lo.x, hi.x);
            P[42 + e*3 + 1] = make_float2(-lo.y, -hi.y);
            P[42 + e*3 + 2] = make_float2(lo.y, hi.y);
        }
        // observables (U3(3)'/U3(7)' folded into Z)
        for (int w = 0; w < 2; w++) {
            const float2* U = su3[br][4 + w];
            float a = fmaf(U[0].x, U[0].x, U[0].y * U[0].y)
                    - fmaf(U[2].x, U[2].x, U[2].y * U[2].y);
            float2 b0 = cjmul(U[0], U[1]);
            float2 b1 = cjmul(U[2], U[3]);
            float bx = 2.f * (b0.x - b1.x);
            float by = 2.f * (b0.y - b1.y);
            float2* O = g_obsp[br][w];
            O[0] = dup(a);   O[1] = dup(-a);
            O[2] = dup(bx);  O[3] = dup(-by);  O[4] = dup(by);
            O[5] = make_float2(0.f, 0.f);
        }
    }
}

// ---------------------------------------------------------------------------
// SoA state: X[k]=(re at j1=0, re at j1=1), Y likewise; k = (j2<<1)|j0.
// Lane bits: l4=q0(16) l3=q1(8) l2=q2(4) l1=q4(2) l0=q6(1).
// ---------------------------------------------------------------------------

// vertical complex 2x2 on register pair (a0=(X0,Y0), a1=(X1,Y1))
static __device__ __forceinline__ void vert_pair(float2& X0, float2& Y0, float2& X1, float2& Y1,
                                                 const float2* __restrict__ C) {
    float2 ox0 = f2mul(C[0], X0);
    ox0 = f2fma(C[1], Y0, ox0);
    ox0 = f2fma(C[3], X1, ox0);
    ox0 = f2fma(C[4], Y1, ox0);
    float2 oy0 = f2mul(C[2], X0);
    oy0 = f2fma(C[0], Y0, oy0);
    oy0 = f2fma(C[5], X1, oy0);
    oy0 = f2fma(C[3], Y1, oy0);
    float2 ox1 = f2mul(C[6], X0);
    ox1 = f2fma(C[7], Y0, ox1);
    ox1 = f2fma(C[9], X1, ox1);
    ox1 = f2fma(C[10], Y1, ox1);
    float2 oy1 = f2mul(C[8], X0);
    oy1 = f2fma(C[6], Y0, oy1);
    oy1 = f2fma(C[11], X1, oy1);
    oy1 = f2fma(C[9], Y1, oy1);
    X0 = ox0; Y0 = oy0; X1 = ox1; Y1 = oy1;
}

// horizontal U3 on the packed (q5) dimension
static __device__ __forceinline__ void horiz_gate(float2 X[4], float2 Y[4],
                                                  const float2* __restrict__ C) {
#pragma unroll
    for (int k = 0; k < 4; k++) {
        float2 XS = swp(X[k]), YS = swp(Y[k]);
        float2 ox = f2mul(C[0], X[k]);
        ox = f2fma(C[1], Y[k], ox);
        ox = f2fma(C[3], XS, ox);
        ox = f2fma(C[4], YS, ox);
        float2 oy = f2mul(C[2], X[k]);
        oy = f2fma(C[0], Y[k], oy);
        oy = f2fma(C[5], XS, oy);
        oy = f2fma(C[3], YS, oy);
        X[k] = ox; Y[k] = oy;
    }
}

// lane-bit U3 (full complex), C = diag/off triplets for this lane half
static __device__ __forceinline__ void lane_u3(float2 X[4], float2 Y[4],
                                               const float2* __restrict__ C, int lm) {
#pragma unroll
    for (int k = 0; k < 4; k++) {
        float2 PX = shfl2(X[k], lm);
        float2 PY = shfl2(Y[k], lm);
        float2 ox = f2mul(C[0], X[k]);
        ox = f2fma(C[1], Y[k], ox);
        ox = f2fma(C[3], PX, ox);
        ox = f2fma(C[4], PY, ox);
        float2 oy = f2mul(C[2], X[k]);
        oy = f2fma(C[0], Y[k], oy);
        oy = f2fma(C[5], PX, oy);
        oy = f2fma(C[3], PY, oy);
        X[k] = ox; Y[k] = oy;
    }
}

// CRX lane gate on one k: o.x = kc*x + kp*py ; o.y = kc*y + kn*px
static __device__ __forceinline__ void crx_lane_k(float2& X, float2& Y, int lm,
                                                  float2 kc, float2 kp, float2 kn) {
    float2 PX = shfl2(X, lm), PY = shfl2(Y, lm);
    float2 nx = f2fma(kp, PY, f2mul(kc, X));
    float2 ny = f2fma(kn, PX, f2mul(kc, Y));
    X = nx; Y = ny;
}

// real CR lane gate on packed real state
static __device__ __forceinline__ void cr_lane_r(float2& R, int lm, float2 kc, float2 ks) {
    float2 P = shfl2(R, lm);
    R = f2fma(ks, P, f2mul(kc, R));
}

// observables: lane-partial values only (warp reduction deferred)
static __device__ __forceinline__ void obs_eval_pk(const float2 X[4], const float2 Y[4],
                                                   const float2* __restrict__ O3,
                                                   const float2* __restrict__ O7,
                                                   float* e3o, float* e7o) {
    float2 q[4];
#pragma unroll
    for (int k = 0; k < 4; k++) q[k] = f2fma(Y[k], Y[k], f2mul(X[k], X[k]));
    float2 E3 = make_float2(0.f, 0.f);
#pragma unroll
    for (int kp = 0; kp < 2; kp++) {
        int kb = kp + 2;
        E3 = f2fma(O3[0], q[kp], E3);
        E3 = f2fma(O3[1], q[kb], E3);
        E3 = f2fma(O3[2], f2mul(X[kp], X[kb]), E3);
        E3 = f2fma(O3[2], f2mul(Y[kp], Y[kb]), E3);
        E3 = f2fma(O3[3], f2mul(X[kp], Y[kb]), E3);
        E3 = f2fma(O3[4], f2mul(Y[kp], X[kb]), E3);
    }
    float2 E7 = make_float2(0.f, 0.f);
#pragma unroll
    for (int kp = 0; kp < 4; kp += 2) {
        int kb = kp + 1;
        E7 = f2fma(O7[0], q[kp], E7);
        E7 = f2fma(O7[1], q[kb], E7);
        E7 = f2fma(O7[2], f2mul(X[kp], X[kb]), E7);
        E7 = f2fma(O7[2], f2mul(Y[kp], Y[kb]), E7);
        E7 = f2fma(O7[3], f2mul(X[kp], Y[kb]), E7);
        E7 = f2fma(O7[4], f2mul(Y[kp], X[kb]), E7);
    }
    *e3o = E3.x + E3.y;
    *e7o = E7.x + E7.y;
}

// ---------------------------------------------------------------------------
// Main kernel: one warp per batch element.
// ---------------------------------------------------------------------------
__global__ void __launch_bounds__(256, 4) qcnn_main(const float* __restrict__ x,
                                                    const float* __restrict__ w1,
                                                    const float* __restrict__ b1,
                                                    const float* __restrict__ w2,
                                                    const float* __restrict__ b2,
                                                    float* __restrict__ out, int batch) {
    __shared__ float2 s_pk[3][54];
    __shared__ float2 s_ob[3][2][6];
    __shared__ float2 s_cr[3][10];
    __shared__ float  s_hz[8];
    __shared__ float  smw1[72];
    __shared__ float  smb1[12];
    __shared__ float  smw2[12];
    __shared__ float  smb2;

    {
        float2* d = &s_pk[0][0];
        const float2* g = &g_pk[0][0];
        for (int i = threadIdx.x; i < 162; i += blockDim.x) d[i] = g[i];
        float2* od = &s_ob[0][0][0];
        const float2* og = &g_obsp[0][0][0];
        for (int i = threadIdx.x; i < 36; i += blockDim.x) od[i] = og[i];
        for (int i = threadIdx.x; i < 72; i += blockDim.x) smw1[i] = w1[i];
        if (threadIdx.x < 30) ((float2*)s_cr)[threadIdx.x] = ((const float2*)g_cr)[threadIdx.x];
        if (threadIdx.x >= 32 && threadIdx.x < 40) s_hz[threadIdx.x - 32] = g_hz[threadIdx.x - 32];
        if (threadIdx.x >= 64 && threadIdx.x < 76) {
            smb1[threadIdx.x - 64] = b1[threadIdx.x - 64];
            smw2[threadIdx.x - 64] = w2[threadIdx.x - 64];
        }
        if (threadIdx.x == 0) smb2 = b2[0];
    }
    __syncthreads();

    int warp = (blockIdx.x * blockDim.x + threadIdx.x) >> 5;
    int lane = threadIdx.x & 31;
    if (warp >= batch) return;

    bool L4 = (lane & 16) != 0, L3 = (lane & 8) != 0, L2 = (lane & 4) != 0,
         L1 = (lane & 2) != 0,  L0 = (lane & 1) != 0;

    // ---- per-qubit (cos, sin) broadcast -----------------------------------
    float xv = 0.f;
    if (lane < 8) xv = x[warp * 8 + lane];
    float sv0, cv0;
    __sincosf(0.5f * xv, &sv0, &cv0);
    float cq[8], sq[8];
#pragma unroll
    for (int q = 0; q < 8; q++) {
        cq[q] = __shfl_sync(FULL, cv0, q);
        sq[q] = __shfl_sync(FULL, sv0, q);
    }
    float u0 = L4 ? sq[0] : cq[0];
    float u2 = L2 ? sq[2] : cq[2];
    float u4 = L1 ? sq[4] : cq[4];
    float u6 = L0 ? sq[6] : cq[6];
    float a1v = L3 ? sq[1] : cq[1];

    float feats[6];

    // ================= RX branch =================
    {
        const float2* cr = s_cr[0];
        const float2* PK = s_pk[0];
        float a1w = L3 ? cq[1] : sq[1];
        float2 f01 = make_float2(u0 * (L4 ? cr[0].x * a1v : a1v),
                                 L4 ? -(u0 * cr[0].y * a1w) : 0.f);
        float cc1 = L2 ? cr[1].x : 1.f, ss1 = L2 ? cr[1].y : 0.f;
        float2 f23a = make_float2(u2 * cc1 * cq[3], -u2 * ss1 * sq[3]);
        float2 f23b = make_float2(u2 * cc1 * sq[3], -u2 * ss1 * cq[3]);
        float cc2 = L1 ? cr[2].x : 1.f, ss2 = L1 ? cr[2].y : 0.f;
        float2 F45x = make_float2(u4 * cc2 * cq[5], u4 * cc2 * sq[5]);
        float2 F45y = make_float2(-u4 * ss2 * sq[5], -u4 * ss2 * cq[5]);
        float cc3 = L0 ? cr[3].x : 1.f, ss3 = L0 ? cr[3].y : 0.f;
        float2 f67a = make_float2(u6 * cc3 * cq[7], -u6 * ss3 * sq[7]);
        float2 f67b = make_float2(u6 * cc3 * sq[7], -u6 * ss3 * cq[7]);
        float2 g0 = cmul(f01, f23a), g1 = cmul(f01, f23b);
        float2 Hx[2], Hy[2];
        Hx[0] = f2fma(dup(-f67a.y), F45y, f2mul(dup(f67a.x), F45x));
        Hy[0] = f2fma(dup(f67a.y), F45x, f2mul(dup(f67a.x), F45y));
        Hx[1] = f2fma(dup(-f67b.y), F45y, f2mul(dup(f67b.x), F45x));
        Hy[1] = f2fma(dup(f67b.y), F45x, f2mul(dup(f67b.x), F45y));
        float2 X[4], Y[4];
#pragma unroll
        for (int k = 0; k < 4; k++) {
            float2 gk = (k & 2) ? g1 : g0;
            int k0 = k & 1;
            X[k] = f2fma(dup(-gk.y), Hy[k0], f2mul(dup(gk.x), Hx[k0]));
            Y[k] = f2fma(dup(gk.y), Hx[k0], f2mul(dup(gk.x), Hy[k0]));
        }
        // CR(1,2): lm=4, lane ctrl L3 (identity-coeff trick)
        {
            float cc = L3 ? cr[4].x : 1.f, ss = L3 ? cr[4].y : 0.f;
            float2 kc = dup(cc), kp = dup(ss), kn = dup(-ss);
#pragma unroll
            for (int k = 0; k < 4; k++) crx_lane_k(X[k], Y[k], 4, kc, kp, kn);
        }
        // CR(3,4): lm=2, ctrl q3 -> k in {2,3}
        {
            float2 kc = dup(cr[5].x), kp = dup(cr[5].y), kn = dup(-cr[5].y);
            crx_lane_k(X[2], Y[2], 2, kc, kp, kn);
            crx_lane_k(X[3], Y[3], 2, kc, kp, kn);
        }
        // CR(5,6): lm=1, ctrl q5 = hi half (per-half coeffs)
        {
            float2 kc = make_float2(1.f, cr[6].x);
            float2 kp = make_float2(0.f, cr[6].y);
            float2 kn = make_float2(0.f, -cr[6].y);
#pragma unroll
            for (int k = 0; k < 4; k++) crx_lane_k(X[k], Y[k], 1, kc, kp, kn);
        }
        lane_u3(X, Y, PK + (L3 ? 6 : 0), 8);    // U3(1)
        horiz_gate(X, Y, PK + 12);              // U3(5)
        {
            const float2* CA = PK + 18 + (L3 ? 12 : 0);
            vert_pair(X[0], Y[0], X[2], Y[2], CA);
            vert_pair(X[1], Y[1], X[3], Y[3], CA);
        }
        {
            const float2* CB = PK + 42;
            vert_pair(X[0], Y[0], X[1], Y[1], CB);
            vert_pair(X[2], Y[2], X[3], Y[3], CB);
        }
        // CR(3,5): horizontal CRX on k in {2,3}
        {
            float2 kc = dup(cr[9].x), kp = dup(cr[9].y), kn = dup(-cr[9].y);
#pragma unroll
            for (int k = 2; k < 4; k++) {
                float2 XS = swp(X[k]), YS = swp(Y[k]);
                X[k] = f2fma(kp, YS, f2mul(kc, X[k]));
                Y[k] = f2fma(kn, XS, f2mul(kc, Y[k]));
            }
        }
        obs_eval_pk(X, Y, s_ob[0][0], s_ob[0][1], &feats[0], &feats[1]);
    }

    // ================= RY branch (pairs1 fully real) =================
    {
        const float2* cr = s_cr[1];
        const float2* PK = s_pk[1];
        float r1 = L3 ? fmaf(cr[0].y, cq[1], cr[0].x * sq[1])
                      : fmaf(cr[0].x, cq[1], -cr[0].y * sq[1]);
        float f01r = u0 * (L4 ? r1 : a1v);
        float cc1 = L2 ? cr[1].x : 1.f, ss1 = L2 ? cr[1].y : 0.f;
        float f23r0 = u2 * fmaf(cc1, cq[3], -ss1 * sq[3]);
        float f23r1 = u2 * fmaf(ss1, cq[3],  cc1 * sq[3]);
        float cc2 = L1 ? cr[2].x : 1.f, ss2 = L1 ? cr[2].y : 0.f;
        float f45r0 = u4 * fmaf(cc2, cq[5], -ss2 * sq[5]);
        float f45r1 = u4 * fmaf(ss2, cq[5],  cc2 * sq[5]);
        float cc3 = L0 ? cr[3].x : 1.f, ss3 = L0 ? cr[3].y : 0.f;
        float f67r0 = u6 * fmaf(cc3, cq[7], -ss3 * sq[7]);
        float f67r1 = u6 * fmaf(ss3, cq[7],  cc3 * sq[7]);
        float g0r = f01r * f23r0, g1r = f01r * f23r1;
        float2 F45 = make_float2(f45r0, f45r1);
        float2 T0 = f2mul(dup(f67r0), F45);
        float2 T1 = f2mul(dup(f67r1), F45);
        float2 RP[4];
        RP[0] = f2mul(dup(g0r), T0);
        RP[1] = f2mul(dup(g0r), T1);
        RP[2] = f2mul(dup(g1r), T0);
        RP[3] = f2mul(dup(g1r), T1);
        // CR(1,2)
        {
            float cc = L3 ? cr[4].x : 1.f, ss = L3 ? cr[4].y : 0.f;
            float2 kc = dup(cc), ks = dup(L2 ? ss : -ss);
#pragma unroll
            for (int k = 0; k < 4; k++) cr_lane_r(RP[k], 4, kc, ks);
        }
        // CR(3,4)
        {
            float2 kc = dup(cr[5].x), ks = dup(L1 ? cr[5].y : -cr[5].y);
            cr_lane_r(RP[2], 2, kc, ks);
            cr_lane_r(RP[3], 2, kc, ks);
        }
        // CR(5,6)
        {
            float2 kc = make_float2(1.f, cr[6].x);
            float2 ks = make_float2(0.f, L0 ? cr[6].y : -cr[6].y);
#pragma unroll
            for (int k = 0; k < 4; k++) cr_lane_r(RP[k], 1, kc, ks);
        }
        // U3(1) real -> complex
        float2 X[4], Y[4];
        {
            const float2* C = PK + (L3 ? 6 : 0);
            float2 cdx = C[0], cdy = C[2], cox = C[3], coy = C[5];
#pragma unroll
            for (int k = 0; k < 4; k++) {
                float2 P = shfl2(RP[k], 8);
                X[k] = f2fma(cox, P, f2mul(cdx, RP[k]));
                Y[k] = f2fma(coy, P, f2mul(cdy, RP[k]));
            }
        }
        horiz_gate(X, Y, PK + 12);              // U3(5)
        {
            const float2* CA = PK + 18 + (L3 ? 12 : 0);
            vert_pair(X[0], Y[0], X[2], Y[2], CA);
            vert_pair(X[1], Y[1], X[3], Y[3], CA);
        }
        {
            const float2* CB = PK + 42;
            vert_pair(X[0], Y[0], X[1], Y[1], CB);
            vert_pair(X[2], Y[2], X[3], Y[3], CB);
        }
        // CR(3,5): horizontal real rotation on k in {2,3}
        {
            float2 kc = dup(cr[9].x);
            float2 S = make_float2(-cr[9].y, cr[9].y);
#pragma unroll
            for (int k = 2; k < 4; k++) {
                float2 XS = swp(X[k]), YS = swp(Y[k]);
                X[k] = f2fma(S, XS, f2mul(kc, X[k]));
                Y[k] = f2fma(S, YS, f2mul(kc, Y[k]));
            }
        }
        obs_eval_pk(X, Y, s_ob[1][0], s_ob[1][1], &feats[2], &feats[3]);
    }

    // ================= RZ branch =================
    {
        const float2* PK = s_pk[2];
        float A0 = u0 * (L3 ? sq[1] : cq[1]) * u2 * u4 * u6;
        float th_lane = 0.f;
        if (lane & 16) th_lane += (lane & 8) ? s_hz[0] : -s_hz[0];  // CR(0,1)
        if (lane & 8)  th_lane += (lane & 4) ? s_hz[4] : -s_hz[4];  // CR(1,2)
        float t1 = L2 ? s_hz[1] : 0.f;                              // CR(2,3)
        float t2 = L1 ? s_hz[2] : 0.f;                              // CR(4,5)
        float t3 = L0 ? s_hz[3] : 0.f;                              // CR(6,7)
        float u5 = L1 ? s_hz[5] : -s_hz[5];                         // CR(3,4)
        float u6z = L0 ? s_hz[6] : -s_hz[6];                        // CR(5,6)
        float2 X[4], Y[4];
#pragma unroll
        for (int j = 0; j < 8; j++) {
            float th = th_lane
                     + ((j & 4) ? t1 : -t1)
                     + ((j & 2) ? t2 : -t2)
                     + ((j & 1) ? t3 : -t3);
            if (j & 4) th += u5;
            if (j & 2) th += u6z;
            float sn, cs;
            __sincosf(th, &sn, &cs);
            float iv = A0 * ((j & 4) ? sq[3] : cq[3])
                          * ((j & 2) ? sq[5] : cq[5])
                          * ((j & 1) ? sq[7] : cq[7]);
            float vx = iv * cs, vy = iv * sn;
            int k = ((j >> 1) & 2) | (j & 1);
            if (j & 2) { X[k].y = vx; Y[k].y = vy; }
            else       { X[k].x = vx; Y[k].x = vy; }
        }
        lane_u3(X, Y, PK + (L3 ? 6 : 0), 8);    // U3(1)
        horiz_gate(X, Y, PK + 12);              // U3(5)
        {
            const float2* CA = PK + 18 + (L3 ? 12 : 0);
            vert_pair(X[0], Y[0], X[2], Y[2], CA);
            vert_pair(X[1], Y[1], X[3], Y[3], CA);
        }
        {
            const float2* CB = PK + 42;
            vert_pair(X[0], Y[0], X[1], Y[1], CB);
            vert_pair(X[2], Y[2], X[3], Y[3], CB);
        }
        // CR(3,5): diagonal phase on k in {2,3}
        {
            float c9 = s_cr[2][9].x, s9 = s_cr[2][9].y;
            float2 kc = dup(c9);
            float2 Sm = make_float2(s9, -s9);
            float2 Sp = make_float2(-s9, s9);
#pragma unroll
            for (int k = 2; k < 4; k++) {
                float2 nx = f2fma(Sm, Y[k], f2mul(kc, X[k]));
                float2 ny = f2fma(Sp, X[k], f2mul(kc, Y[k]));
                X[k] = nx; Y[k] = ny;
            }
        }
        obs_eval_pk(X, Y, s_ob[2][0], s_ob[2][1], &feats[4], &feats[5]);
    }

    // ---- deferred warp reduction of all 6 features (interleaved butterflies) ---
#pragma unroll
    for (int o = 16; o > 0; o >>= 1) {
#pragma unroll
        for (int f = 0; f < 6; f++) feats[f] += __shfl_xor_sync(FULL, feats[f], o);
    }

    // ---- MLP ----------------------------------------------------------------
    float term = 0.f;
    if (lane < 12) {
        float z = smb1[lane];
#pragma unroll
        for (int j = 0; j < 6; j++) z = fmaf(smw1[lane * 6 + j], feats[j], z);
        term = smw2[lane] * tanhf(z);
    }
#pragma unroll
    for (int o = 8; o > 0; o >>= 1) term += __shfl_xor_sync(FULL, term, o);
    if (lane == 0) {
        float z2 = smb2 + term;
        out[warp] = 1.f / (1.f + expf(-z2));
    }
}

extern "C" void kernel_launch(void* const* d_in, const int* in_sizes, int n_in,
                              void* d_out, int out_size) {
    const float* x   = (const float*)d_in[0];
    const float* crx = (const float*)d_in[1];
    const float* u3x = (const float*)d_in[2];
    const float* cry = (const float*)d_in[3];
    const float* u3y = (const float*)d_in[4];
    const float* crz = (const float*)d_in[5];
    const float* u3z = (const float*)d_in[6];
    const float* w1  = (const float*)d_in[7];
    const float* b1  = (const float*)d_in[8];
    const float* w2  = (const float*)d_in[9];
    const float* b2  = (const float*)d_in[10];
    float* out = (float*)d_out;

    int batch = in_sizes[0] / NQ;

    qcnn_precompute<<<1, 64>>>(crx, u3x, cry, u3y, crz, u3z);

    int threads = 256;   // 8 warps per block
    int blocks = (batch * 32 + threads - 1) / threads;
    qcnn_main<<<blocks, threads>>>(x, w1, b1, w2, b2, out, batch);
}